// round 13
// baseline (speedup 1.0000x reference)
#include <cuda_runtime.h>
#include <cstdint>

#define B_ 32
#define I_ 1152
#define IH 576          // i-half per CTA
#define O_ 10
#define D_ 16
#define H_ 10
#define S_ 922
#define SH 461          // samples per CTA
#define T_ 512
#define PAD 20          // s_u row stride (floats)
#define RS (O_ * D_)    // 160

// dynamic smem layout (floats)
#define OFF_U    0
#define OFF_VM   (IH * PAD)            // interleaved (vn, mask)
#define OFF_NUM  (OFF_VM + 2 * IH)
#define OFF_DEN  (OFF_NUM + H_ * D_)
#define OFF_LOSS (OFF_DEN + 16)
#define SMEM_FLOATS (OFF_LOSS + 16)    // 12864 floats -> 51456 B

__device__ __forceinline__ float sqrt_approx(float x) {
    float y;
    asm("sqrt.approx.f32 %0, %1;" : "=f"(y) : "f"(x));
    return y;
}
__device__ __forceinline__ uint32_t mapa_peer(uint32_t addr, uint32_t rank) {
    uint32_t r;
    asm("mapa.shared::cluster.u32 %0, %1, %2;" : "=r"(r) : "r"(addr), "r"(rank));
    return r;
}
__device__ __forceinline__ float ld_cluster_f32(uint32_t addr) {
    float v;
    asm volatile("ld.shared::cluster.f32 %0, [%1];" : "=f"(v) : "r"(addr));
    return v;
}
__device__ __forceinline__ void red_or_cluster(uint32_t addr, unsigned val) {
    asm volatile("red.relaxed.cluster.shared::cluster.or.b32 [%0], %1;"
                 :: "r"(addr), "r"(val) : "memory");
}
#define CLUSTER_SYNC() do { \
    asm volatile("barrier.cluster.arrive.aligned;" ::: "memory"); \
    asm volatile("barrier.cluster.wait.aligned;"   ::: "memory"); \
} while (0)

// ---------------------------------------------------------------------------
// Cluster of 2 CTAs per (b,o); each owns an i-half in smem; 4 CTAs/SM.
//  0:  probe; zero; load u half + vn
//  0b: scatter OWN SAMPLE-HALF (1 iter/thread), bits routed by DSMEM red.or
//  1:  masked accumulation -> partial num/den
//  Mu: exchange partials via DSMEM -> full Mu both CTAs; mu2
//  2:  butterfly losses, 5 groups of 2 h (8 mq regs -> fits 32-reg budget)
//  rank0 argmin via peer loss + output
// ---------------------------------------------------------------------------
__global__ void __cluster_dims__(2, 1, 1) __launch_bounds__(T_, 4)
fused_kernel(const float* __restrict__ u, const int* __restrict__ idx,
             float* __restrict__ out) {
    extern __shared__ float sm[];
    float* s_u     = sm + OFF_U;                   // [576][PAD]
    float* s_vm    = sm + OFF_VM;                  // [576][2] (vn, mask)
    float* s_num   = sm + OFF_NUM;                 // [H][D]
    float* s_den   = sm + OFF_DEN;                 // [H]
    float* s_lossH = sm + OFF_LOSS;                // [H]

    __shared__ __align__(16) float s_Mu[H_][D_];
    __shared__ float s_mu2[H_];
    __shared__ float s_loss[16][H_];
    __shared__ int   s_is64;

    uint32_t rank;
    asm("mov.u32 %0, %%cluster_ctarank;" : "=r"(rank));
    const int bo   = blockIdx.x >> 1;
    const int b    = bo / O_;
    const int o    = bo % O_;
    const int i0   = (int)rank * IH;
    const int tid  = threadIdx.x;
    const int lane = tid & 31;
    const int w    = tid >> 5;      // 16 warps

    const float* ub = u + ((size_t)b * I_ * O_ + o) * D_;

    // ---- phase 0: dtype probe + zero + load u half + vn ----
    if (w == 0) {
        unsigned v = ((const unsigned*)idx)[2 * lane + 1]
                   | ((const unsigned*)idx)[2 * (lane + 32) + 1];
        unsigned r = __reduce_or_sync(0xffffffffu, v);
        if (lane == 0) s_is64 = (r == 0u) ? 1 : 0;
    }
    for (int j = tid; j < IH; j += T_) s_vm[2 * j + 1] = 0.f;
    if (tid < H_ * D_) s_num[tid] = 0.f;

#pragma unroll 1
    for (int e = tid; e < IH * 4; e += T_) {       // 4.5 iters, warp-uniform
        int row = e >> 2, j = e & 3;
        float4 q = *(const float4*)(ub + (size_t)(i0 + row) * RS + j * 4);
        *(float4*)(s_u + row * PAD + j * 4) = q;
        float p = q.x * q.x + q.y * q.y + q.z * q.z + q.w * q.w;
        p += __shfl_xor_sync(0xffffffffu, p, 1);
        p += __shfl_xor_sync(0xffffffffu, p, 2);
        if (j == 0) s_vm[2 * row] = sqrt_approx(p);
    }
    __syncthreads();
    CLUSTER_SYNC();                                // peer mask-zeroing visible

    // ---- phase 0b: scatter own sample-half; route bits via DSMEM red.or ----
#define SCATTER1(IG, HBIT) do {                                               \
        int _i = (IG);                                                        \
        unsigned _own = (_i >= IH) ? 1u : 0u;                                 \
        int _li = _own ? _i - IH : _i;                                        \
        uint32_t _la = (uint32_t)__cvta_generic_to_shared(&s_vm[2 * _li + 1]);\
        red_or_cluster(mapa_peer(_la, _own), 1u << (HBIT));                   \
    } while (0)

    if (s_is64) {
#pragma unroll 1
        for (int s = (int)rank * SH + tid; s < (int)(rank + 1) * SH; s += T_) {
            int base = ((b * S_ + s) * O_ + o) * H_;
            const int4* p = (const int4*)idx + (base >> 1);
            int4 a0 = p[0], a1 = p[1], a2 = p[2], a3 = p[3], a4 = p[4];
            SCATTER1(a0.x, 0); SCATTER1(a0.z, 1);
            SCATTER1(a1.x, 2); SCATTER1(a1.z, 3);
            SCATTER1(a2.x, 4); SCATTER1(a2.z, 5);
            SCATTER1(a3.x, 6); SCATTER1(a3.z, 7);
            SCATTER1(a4.x, 8); SCATTER1(a4.z, 9);
        }
    } else {
#pragma unroll 1
        for (int s = (int)rank * SH + tid; s < (int)(rank + 1) * SH; s += T_) {
            int base = ((b * S_ + s) * O_ + o) * H_;
            const int2* p = (const int2*)idx + (base >> 1);
            int2 a0 = p[0], a1 = p[1], a2 = p[2], a3 = p[3], a4 = p[4];
            SCATTER1(a0.x, 0); SCATTER1(a0.y, 1);
            SCATTER1(a1.x, 2); SCATTER1(a1.y, 3);
            SCATTER1(a2.x, 4); SCATTER1(a2.y, 5);
            SCATTER1(a3.x, 6); SCATTER1(a3.y, 7);
            SCATTER1(a4.x, 8); SCATTER1(a4.y, 9);
        }
    }
#undef SCATTER1
    CLUSTER_SYNC();                                // all red.or complete

    // ---- phase 1: masked accumulation over own half ----
    {
        const int d  = lane & 15;
        const int hb = (lane >> 4) * 5;
        float a0 = 0.f, a1 = 0.f, a2 = 0.f, a3 = 0.f, a4 = 0.f;
#pragma unroll 4
        for (int ii = w; ii < IH; ii += 16) {      // 36 iterations
            float2   vm = *(const float2*)&s_vm[2 * ii];
            unsigned m  = __float_as_uint(vm.y) >> hb;
            float    t0 = vm.x * s_u[ii * PAD + d];
            if (m & 1u)  a0 += t0;
            if (m & 2u)  a1 += t0;
            if (m & 4u)  a2 += t0;
            if (m & 8u)  a3 += t0;
            if (m & 16u) a4 += t0;
        }
        atomicAdd(&s_num[(hb + 0) * D_ + d], a0);
        atomicAdd(&s_num[(hb + 1) * D_ + d], a1);
        atomicAdd(&s_num[(hb + 2) * D_ + d], a2);
        atomicAdd(&s_num[(hb + 3) * D_ + d], a3);
        atomicAdd(&s_num[(hb + 4) * D_ + d], a4);
    }
    if (w < H_) {                                  // den, one h per warp
        unsigned bit = 1u << w;
        float dn = 0.f;
#pragma unroll 4
        for (int ii = lane; ii < IH; ii += 32) {
            float2 vm = *(const float2*)&s_vm[2 * ii];
            if (__float_as_uint(vm.y) & bit) dn += vm.x;
        }
#pragma unroll
        for (int off = 16; off > 0; off >>= 1)
            dn += __shfl_down_sync(0xffffffffu, dn, off);
        if (lane == 0) s_den[w] = dn;
    }
    __syncthreads();

    // ---- exchange partials; build full Mu (both CTAs identical) ----
    CLUSTER_SYNC();
    if (tid < H_ * D_) {
        int h = tid >> 4;
        uint32_t pn = mapa_peer((uint32_t)__cvta_generic_to_shared(&s_num[tid]),
                                rank ^ 1u);
        uint32_t pd = mapa_peer((uint32_t)__cvta_generic_to_shared(&s_den[h]),
                                rank ^ 1u);
        float num = s_num[tid] + ld_cluster_f32(pn);
        float den = s_den[h]   + ld_cluster_f32(pd);
        s_Mu[h][tid & 15] = num / den;
    }
    __syncthreads();
    if (tid < H_) {
        float m2 = 0.f;
#pragma unroll
        for (int dd = 0; dd < D_; dd++) { float x = s_Mu[tid][dd]; m2 += x * x; }
        s_mu2[tid] = m2;
    }
    __syncthreads();

    // ---- phase 2: butterfly losses, 5 groups of 2 h (low reg pressure) ----
    {
        const int dq  = tid & 3;
        const int g   = tid >> 2;                  // 0..127
        const int sel = lane & 1;
#pragma unroll 1
        for (int grp = 0; grp < 5; grp++) {
            float4 ma = *(const float4*)(&s_Mu[2 * grp + 0][dq * 4]);
            float4 mb = *(const float4*)(&s_Mu[2 * grp + 1][dq * 4]);
            const float u2 = s_mu2[2 * grp + sel];
            float lacc = 0.f;
#pragma unroll 1
            for (int k = 0; k < 5; k++) {          // 4.5 iters, warp-uniform
                int i = g + k * 128;
                if (i < IH) {
                    float4 q = *(const float4*)(s_u + i * PAD + dq * 4);
                    float  v = s_vm[2 * i];
                    float sq = v * v;
                    float pa = q.x*ma.x + q.y*ma.y + q.z*ma.z + q.w*ma.w;
                    float pb = q.x*mb.x + q.y*mb.y + q.z*mb.z + q.w*mb.w;
                    float keep = sel ? pb : pa;
                    float send = sel ? pa : pb;
                    float C = keep + __shfl_xor_sync(0xffffffffu, send, 1);
                    float dot = C + __shfl_xor_sync(0xffffffffu, C, 2);
                    lacc += sqrt_approx(fmaxf(sq + fmaf(-2.f, dot, u2), 0.f));
                }
            }
            lacc += __shfl_down_sync(0xffffffffu, lacc, 16);
            lacc += __shfl_down_sync(0xffffffffu, lacc, 8);
            lacc += __shfl_down_sync(0xffffffffu, lacc, 4);
            if (lane < 2) s_loss[w][2 * grp + lane] = lacc;  // x2 dup, uniform
        }
    }
    __syncthreads();
    if (tid < H_) {
        float l = 0.f;
#pragma unroll
        for (int ww = 0; ww < 16; ww++) l += s_loss[ww][tid];
        s_lossH[tid] = l;
    }
    __syncthreads();

    // ---- exchange loss halves; rank 0 argmin + output ----
    CLUSTER_SYNC();
    if (rank == 0 && w == 0) {
        float myv = 3.4e38f;
        int   myh = 0;
        if (lane < H_) {
            uint32_t pl = mapa_peer(
                (uint32_t)__cvta_generic_to_shared(&s_lossH[lane]), 1u);
            myv = s_lossH[lane] + ld_cluster_f32(pl);
            myh = lane;
        }
#pragma unroll
        for (int off = 16; off > 0; off >>= 1) {
            float ov = __shfl_xor_sync(0xffffffffu, myv, off);
            int   oh = __shfl_xor_sync(0xffffffffu, myh, off);
            if (ov < myv || (ov == myv && oh < myh)) { myv = ov; myh = oh; }
        }
        if (lane < D_) out[(size_t)bo * D_ + lane] = s_Mu[myh][lane];
    }
    CLUSTER_SYNC();   // peer smem must outlive rank0's reads
}

// ---------------------------------------------------------------------------
extern "C" void kernel_launch(void* const* d_in, const int* in_sizes, int n_in,
                              void* d_out, int out_size) {
    const float* u   = (const float*)d_in[0];
    const int*   idx = (const int*)d_in[1];
    float*       out = (float*)d_out;
    (void)in_sizes; (void)n_in; (void)out_size;

    const int dynSmem = SMEM_FLOATS * 4;   // 51456 bytes
    static int attr_set = 0;
    if (!attr_set) {
        cudaFuncSetAttribute(fused_kernel,
                             cudaFuncAttributeMaxDynamicSharedMemorySize, dynSmem);
        attr_set = 1;
    }
    fused_kernel<<<2 * B_ * O_, T_, dynSmem>>>(u, idx, out);
}

// round 14
// speedup vs baseline: 1.6379x; 1.6379x over previous
#include <cuda_runtime.h>
#include <cstdint>

#define B_ 32
#define I_ 1152
#define IH 576          // i-half per CTA
#define O_ 10
#define D_ 16
#define H_ 10
#define S_ 922
#define SH 461          // samples per CTA (922/2)
#define T_ 256
#define PAD 20          // s_u row stride (floats)
#define RS (O_ * D_)    // 160

// dynamic smem layout (floats)
#define OFF_U     0
#define OFF_MASKF (IH * PAD)              // 11520: FULL-range mask [1152]
#define OFF_VN    (OFF_MASKF + I_)        // 12672: vn own half [576]
#define OFF_NUM   (OFF_VN + IH)           // 13248: [H][D]
#define OFF_DEN   (OFF_NUM + H_ * D_)     // 13408
#define OFF_LOSS  (OFF_DEN + 16)          // 13424
#define SMEM_FLOATS (OFF_LOSS + 16)       // 13440 -> 53760 B

__device__ __forceinline__ float sqrt_approx(float x) {
    float y;
    asm("sqrt.approx.f32 %0, %1;" : "=f"(y) : "f"(x));
    return y;
}
__device__ __forceinline__ uint32_t mapa_peer(uint32_t addr, uint32_t rank) {
    uint32_t r;
    asm("mapa.shared::cluster.u32 %0, %1, %2;" : "=r"(r) : "r"(addr), "r"(rank));
    return r;
}
__device__ __forceinline__ float ld_cluster_f32(uint32_t addr) {
    float v;
    asm volatile("ld.shared::cluster.f32 %0, [%1];" : "=f"(v) : "r"(addr));
    return v;
}
__device__ __forceinline__ unsigned ld_cluster_u32(uint32_t addr) {
    unsigned v;
    asm volatile("ld.shared::cluster.u32 %0, [%1];" : "=r"(v) : "r"(addr));
    return v;
}
#define CLUSTER_SYNC() do { \
    asm volatile("barrier.cluster.arrive.aligned;" ::: "memory"); \
    asm volatile("barrier.cluster.wait.aligned;"   ::: "memory"); \
} while (0)

// ---------------------------------------------------------------------------
// Cluster of 2 CTAs per (b,o); each owns an i-half (u, vn) + a FULL-range
// local mask. 256 threads, ~54KB smem -> 4 CTAs/SM -> 640 CTAs in 1.08 waves.
//  0:  probe; zero mask; load u half + vn
//  0b: scatter own SAMPLE-half locally (unfiltered, 2 iters); bulk DSMEM
//      merge of my-half mask bits from peer (disjoint regions)
//  1:  masked accumulation over own i-half -> partial num/den
//  Mu: DSMEM exchange of num/den -> full Mu in both CTAs; mu2
//  2:  R10-style butterfly losses (grp4,grp4,grp2), 9 exact k-iters
//  rank0: argmin with peer loss, output
// ---------------------------------------------------------------------------
__global__ void __cluster_dims__(2, 1, 1) __launch_bounds__(T_, 4)
fused_kernel(const float* __restrict__ u, const int* __restrict__ idx,
             float* __restrict__ out) {
    extern __shared__ float sm[];
    float*    s_u     = sm + OFF_U;                  // [576][PAD]
    unsigned* s_maskF = (unsigned*)(sm + OFF_MASKF); // [1152]
    float*    s_vn    = sm + OFF_VN;                 // [576]
    float*    s_num   = sm + OFF_NUM;                // [H][D]
    float*    s_den   = sm + OFF_DEN;                // [H]
    float*    s_lossH = sm + OFF_LOSS;               // [H]

    __shared__ __align__(16) float s_Mu[H_][D_];
    __shared__ float s_mu2[H_];
    __shared__ float s_loss[8][H_];
    __shared__ int   s_is64;

    uint32_t rank;
    asm("mov.u32 %0, %%cluster_ctarank;" : "=r"(rank));
    const int bo   = blockIdx.x >> 1;
    const int b    = bo / O_;
    const int o    = bo % O_;
    const int i0   = (int)rank * IH;
    const int tid  = threadIdx.x;
    const int lane = tid & 31;
    const int w    = tid >> 5;      // 8 warps

    const float* ub = u + ((size_t)b * I_ * O_ + o) * D_;

    // ---- phase 0: dtype probe + zero full mask + load u half + vn ----
    if (w == 0) {
        unsigned v = ((const unsigned*)idx)[2 * lane + 1]
                   | ((const unsigned*)idx)[2 * (lane + 32) + 1];
        unsigned r = __reduce_or_sync(0xffffffffu, v);
        if (lane == 0) s_is64 = (r == 0u) ? 1 : 0;
    }
    for (int j = tid; j < I_; j += T_) s_maskF[j] = 0u;
    if (tid < H_ * D_) s_num[tid] = 0.f;

#pragma unroll 1
    for (int e = tid; e < IH * 4; e += T_) {        // 9 exact iters
        int row = e >> 2, j = e & 3;
        float4 q = *(const float4*)(ub + (size_t)(i0 + row) * RS + j * 4);
        *(float4*)(s_u + row * PAD + j * 4) = q;
        float p = q.x * q.x + q.y * q.y + q.z * q.z + q.w * q.w;
        p += __shfl_xor_sync(0xffffffffu, p, 1);
        p += __shfl_xor_sync(0xffffffffu, p, 2);
        if (j == 0) s_vn[row] = sqrt_approx(p);
    }
    __syncthreads();

    // ---- phase 0b: scatter own sample-half, LOCAL + unfiltered ----
    if (s_is64) {
#pragma unroll 1
        for (int s = (int)rank * SH + tid; s < (int)rank * SH + SH; s += T_) {
            int base = ((b * S_ + s) * O_ + o) * H_;
            const int4* p = (const int4*)idx + (base >> 1);
            int4 a0 = p[0], a1 = p[1], a2 = p[2], a3 = p[3], a4 = p[4];
            atomicOr(&s_maskF[a0.x], 1u << 0);
            atomicOr(&s_maskF[a0.z], 1u << 1);
            atomicOr(&s_maskF[a1.x], 1u << 2);
            atomicOr(&s_maskF[a1.z], 1u << 3);
            atomicOr(&s_maskF[a2.x], 1u << 4);
            atomicOr(&s_maskF[a2.z], 1u << 5);
            atomicOr(&s_maskF[a3.x], 1u << 6);
            atomicOr(&s_maskF[a3.z], 1u << 7);
            atomicOr(&s_maskF[a4.x], 1u << 8);
            atomicOr(&s_maskF[a4.z], 1u << 9);
        }
    } else {
#pragma unroll 1
        for (int s = (int)rank * SH + tid; s < (int)rank * SH + SH; s += T_) {
            int base = ((b * S_ + s) * O_ + o) * H_;
            const int2* p = (const int2*)idx + (base >> 1);
            int2 a0 = p[0], a1 = p[1], a2 = p[2], a3 = p[3], a4 = p[4];
            atomicOr(&s_maskF[a0.x], 1u << 0);
            atomicOr(&s_maskF[a0.y], 1u << 1);
            atomicOr(&s_maskF[a1.x], 1u << 2);
            atomicOr(&s_maskF[a1.y], 1u << 3);
            atomicOr(&s_maskF[a2.x], 1u << 4);
            atomicOr(&s_maskF[a2.y], 1u << 5);
            atomicOr(&s_maskF[a3.x], 1u << 6);
            atomicOr(&s_maskF[a3.y], 1u << 7);
            atomicOr(&s_maskF[a4.x], 1u << 8);
            atomicOr(&s_maskF[a4.y], 1u << 9);
        }
    }
    __syncthreads();
    CLUSTER_SYNC();     // peer's local scatter visible

    // ---- bulk merge: my-half mask |= peer's bits for my i-range ----
    {
        uint32_t myBase   = (uint32_t)__cvta_generic_to_shared(s_maskF);
        uint32_t peerBase = mapa_peer(myBase, rank ^ 1u);
#pragma unroll 1
        for (int i = tid; i < IH; i += T_) {        // 2.25 iters
            unsigned pm = ld_cluster_u32(peerBase + 4u * (i0 + i));
            s_maskF[i0 + i] |= pm;
        }
    }
    __syncthreads();

    // ---- phase 1: masked accumulation over own i-half ----
    {
        const int d  = lane & 15;
        const int hb = (lane >> 4) * 5;
        float a0 = 0.f, a1 = 0.f, a2 = 0.f, a3 = 0.f, a4 = 0.f;
#pragma unroll 4
        for (int ii = w; ii < IH; ii += 8) {        // 72 iterations
            unsigned m  = s_maskF[i0 + ii] >> hb;
            float    t0 = s_vn[ii] * s_u[ii * PAD + d];
            if (m & 1u)  a0 += t0;
            if (m & 2u)  a1 += t0;
            if (m & 4u)  a2 += t0;
            if (m & 8u)  a3 += t0;
            if (m & 16u) a4 += t0;
        }
        atomicAdd(&s_num[(hb + 0) * D_ + d], a0);
        atomicAdd(&s_num[(hb + 1) * D_ + d], a1);
        atomicAdd(&s_num[(hb + 2) * D_ + d], a2);
        atomicAdd(&s_num[(hb + 3) * D_ + d], a3);
        atomicAdd(&s_num[(hb + 4) * D_ + d], a4);
    }
    // den: warps 0..7 -> h=w; warps 0,1 also h=8,9
    {
        for (int rep = 0; rep < 2; rep++) {
            int h = (rep == 0) ? w : 8 + w;
            if (rep == 1 && w >= 2) break;
            unsigned bit = 1u << h;
            float dn = 0.f;
#pragma unroll 4
            for (int ii = lane; ii < IH; ii += 32)
                if (s_maskF[i0 + ii] & bit) dn += s_vn[ii];
#pragma unroll
            for (int off = 16; off > 0; off >>= 1)
                dn += __shfl_down_sync(0xffffffffu, dn, off);
            if (lane == 0) s_den[h] = dn;
        }
    }
    __syncthreads();
    CLUSTER_SYNC();     // partial num/den visible cluster-wide

    // ---- exchange num/den; full Mu in both CTAs ----
    if (tid < H_ * D_) {
        int h = tid >> 4;
        uint32_t pn = mapa_peer((uint32_t)__cvta_generic_to_shared(&s_num[tid]),
                                rank ^ 1u);
        uint32_t pd = mapa_peer((uint32_t)__cvta_generic_to_shared(&s_den[h]),
                                rank ^ 1u);
        float num = s_num[tid] + ld_cluster_f32(pn);
        float den = s_den[h]   + ld_cluster_f32(pd);
        s_Mu[h][tid & 15] = num / den;
    }
    __syncthreads();
    if (tid < H_) {
        float m2 = 0.f;
#pragma unroll
        for (int dd = 0; dd < D_; dd++) { float x = s_Mu[tid][dd]; m2 += x * x; }
        s_mu2[tid] = m2;
    }
    __syncthreads();

    // ---- phase 2: butterfly losses (grp4 x2 + grp2), 9 exact k-iters ----
    {
        const int dq   = tid & 3;
        const int g    = tid >> 2;            // 0..63
        const int sel  = lane & 1;
        const int bit1 = (lane >> 1) & 1;

#pragma unroll 1
        for (int grp = 0; grp < 2; grp++) {
            const int hb = grp * 4;
            float4 mq0 = *(const float4*)(&s_Mu[hb + 0][dq * 4]);
            float4 mq1 = *(const float4*)(&s_Mu[hb + 1][dq * 4]);
            float4 mq2 = *(const float4*)(&s_Mu[hb + 2][dq * 4]);
            float4 mq3 = *(const float4*)(&s_Mu[hb + 3][dq * 4]);
            const float u2 = s_mu2[hb + 2 * bit1 + sel];
            float lacc = 0.f;
#pragma unroll 1
            for (int k = 0; k < IH / 64; k++) {   // 9 iterations
                int i = g + k * 64;
                float4 q = *(const float4*)(s_u + i * PAD + dq * 4);
                float  v = s_vn[i];
                float sq = v * v;
                float p0 = q.x*mq0.x + q.y*mq0.y + q.z*mq0.z + q.w*mq0.w;
                float p1 = q.x*mq1.x + q.y*mq1.y + q.z*mq1.z + q.w*mq1.w;
                float p2 = q.x*mq2.x + q.y*mq2.y + q.z*mq2.z + q.w*mq2.w;
                float p3 = q.x*mq3.x + q.y*mq3.y + q.z*mq3.z + q.w*mq3.w;
                float keep_lo = sel ? p1 : p0;
                float send_lo = sel ? p0 : p1;
                float C_lo = keep_lo + __shfl_xor_sync(0xffffffffu, send_lo, 1);
                float keep_hi = sel ? p3 : p2;
                float send_hi = sel ? p2 : p3;
                float C_hi = keep_hi + __shfl_xor_sync(0xffffffffu, send_hi, 1);
                float keep2 = bit1 ? C_hi : C_lo;
                float send2 = bit1 ? C_lo : C_hi;
                float dot = keep2 + __shfl_xor_sync(0xffffffffu, send2, 2);
                lacc += sqrt_approx(fmaxf(sq + fmaf(-2.f, dot, u2), 0.f));
            }
            lacc += __shfl_down_sync(0xffffffffu, lacc, 16);
            lacc += __shfl_down_sync(0xffffffffu, lacc, 8);
            lacc += __shfl_down_sync(0xffffffffu, lacc, 4);
            if (lane < 4) s_loss[w][hb + lane] = lacc;
        }
        {
            float4 m8 = *(const float4*)(&s_Mu[8][dq * 4]);
            float4 m9 = *(const float4*)(&s_Mu[9][dq * 4]);
            const float u2 = s_mu2[8 + sel];
            float lacc = 0.f;
#pragma unroll 1
            for (int k = 0; k < IH / 64; k++) {
                int i = g + k * 64;
                float4 q = *(const float4*)(s_u + i * PAD + dq * 4);
                float  v = s_vn[i];
                float sq = v * v;
                float p8 = q.x*m8.x + q.y*m8.y + q.z*m8.z + q.w*m8.w;
                float p9 = q.x*m9.x + q.y*m9.y + q.z*m9.z + q.w*m9.w;
                float keep = sel ? p9 : p8;
                float send = sel ? p8 : p9;
                float C = keep + __shfl_xor_sync(0xffffffffu, send, 1);
                float dot = C + __shfl_xor_sync(0xffffffffu, C, 2);
                lacc += sqrt_approx(fmaxf(sq + fmaf(-2.f, dot, u2), 0.f));
            }
            lacc += __shfl_down_sync(0xffffffffu, lacc, 16);
            lacc += __shfl_down_sync(0xffffffffu, lacc, 8);
            lacc += __shfl_down_sync(0xffffffffu, lacc, 4);
            if (lane < 2) s_loss[w][8 + lane] = lacc;
        }
    }
    __syncthreads();
    if (tid < H_) {
        float l = 0.f;
#pragma unroll
        for (int ww = 0; ww < 8; ww++) l += s_loss[ww][tid];
        s_lossH[tid] = l;
    }
    __syncthreads();
    CLUSTER_SYNC();     // loss halves visible

    // ---- rank 0: argmin with peer loss + output ----
    if (rank == 0 && w == 0) {
        float myv = 3.4e38f;
        int   myh = 0;
        if (lane < H_) {
            uint32_t pl = mapa_peer(
                (uint32_t)__cvta_generic_to_shared(&s_lossH[lane]), 1u);
            myv = s_lossH[lane] + ld_cluster_f32(pl);
            myh = lane;
        }
#pragma unroll
        for (int off = 16; off > 0; off >>= 1) {
            float ov = __shfl_xor_sync(0xffffffffu, myv, off);
            int   oh = __shfl_xor_sync(0xffffffffu, myh, off);
            if (ov < myv || (ov == myv && oh < myh)) { myv = ov; myh = oh; }
        }
        if (lane < D_) out[(size_t)bo * D_ + lane] = s_Mu[myh][lane];
    }
    CLUSTER_SYNC();     // peer smem must outlive rank0's reads
}

// ---------------------------------------------------------------------------
extern "C" void kernel_launch(void* const* d_in, const int* in_sizes, int n_in,
                              void* d_out, int out_size) {
    const float* u   = (const float*)d_in[0];
    const int*   idx = (const int*)d_in[1];
    float*       out = (float*)d_out;
    (void)in_sizes; (void)n_in; (void)out_size;

    const int dynSmem = SMEM_FLOATS * 4;   // 53760 bytes
    static int attr_set = 0;
    if (!attr_set) {
        cudaFuncSetAttribute(fused_kernel,
                             cudaFuncAttributeMaxDynamicSharedMemorySize, dynSmem);
        attr_set = 1;
    }
    fused_kernel<<<2 * B_ * O_, T_, dynSmem>>>(u, idx, out);
}

// round 16
// speedup vs baseline: 1.9675x; 1.2012x over previous
#include <cuda_runtime.h>
#include <cuda_fp16.h>
#include <cstdint>

#define B_ 32
#define I_ 1152
#define O_ 10
#define D_ 16
#define H_ 10
#define S_ 922
#define T_ 512
#define RS (O_ * D_)    // 160

// dynamic smem layout
//   u16  : [1152][16] half  = 36864 B
//   vn   : [1152] float     =  4608 B
//   mask : [1152] unsigned  =  4608 B
#define U16_HALFS (I_ * D_)
#define SMEM_BYTES (U16_HALFS * 2 + I_ * 4 + I_ * 4)   // 46080

__device__ __forceinline__ float sqrt_approx(float x) {
    float y;
    asm("sqrt.approx.f32 %0, %1;" : "=f"(y) : "f"(x));
    return y;
}

// ---------------------------------------------------------------------------
// One CTA per (b,o); u staged in smem as fp16 -> 46KB -> 3 CTAs/SM -> the
// 320-CTA grid runs in ONE wave at 48 warps/SM.
//  0:  dtype probe (safe), zero, load u (fp32 LDG) -> vn fp32 + u16 smem
//  0b: vectorized idx gather -> smem atomicOr bitmask
//  1:  masked weighted accumulation -> Mu numerators (5 acc/thread)
//  1b: den pass (10 warps); Mu = num/den (fp32); mu2
//  2:  butterfly losses (grp4,grp4,grp2), u16->fp32 cvt in loop
//  argmin by warp 0, emit Mu[h*]
// ---------------------------------------------------------------------------
__global__ void __launch_bounds__(T_, 3) fused_kernel(const float* __restrict__ u,
                                                      const int* __restrict__ idx,
                                                      float* __restrict__ out) {
    extern __shared__ char smraw[];
    __half*   s_u16  = (__half*)smraw;                         // [1152][16]
    float*    s_vn   = (float*)(smraw + U16_HALFS * 2);        // [1152]
    unsigned* s_mask = (unsigned*)(s_vn + I_);                 // [1152]

    __shared__ float s_MuNum[H_ * D_];
    __shared__ float s_den[H_];
    __shared__ __align__(16) float s_Mu[H_][D_];
    __shared__ float s_mu2[H_];
    __shared__ float s_loss[16][H_];
    __shared__ int   s_is64;

    const int bo   = blockIdx.x;
    const int b    = bo / O_;
    const int o    = bo % O_;
    const int tid  = threadIdx.x;
    const int lane = tid & 31;
    const int w    = tid >> 5;      // warp 0..15

    const float* ub = u + ((size_t)b * I_ * O_ + o) * D_;

    // ---- phase 0: dtype probe + zero + load u (fp32) -> vn + u16 ----
    if (w == 0) {
        unsigned v = ((const unsigned*)idx)[2 * lane + 1]
                   | ((const unsigned*)idx)[2 * (lane + 32) + 1];
        unsigned r = __reduce_or_sync(0xffffffffu, v);
        if (lane == 0) s_is64 = (r == 0u) ? 1 : 0;
    }
    for (int j = tid; j < I_; j += T_) s_mask[j] = 0u;
    if (tid < H_ * D_) s_MuNum[tid] = 0.f;

#pragma unroll 1
    for (int e = tid; e < I_ * 4; e += T_) {       // 9 exact iterations
        int i = e >> 2, j = e & 3;
        float4 q = *(const float4*)(ub + (size_t)i * RS + j * 4);
        __half2* hp = (__half2*)(s_u16 + i * D_ + j * 4);
        hp[0] = __floats2half2_rn(q.x, q.y);
        hp[1] = __floats2half2_rn(q.z, q.w);
        // fp32 partial squared norm + quad reduce
        float p = q.x * q.x + q.y * q.y + q.z * q.z + q.w * q.w;
        p += __shfl_xor_sync(0xffffffffu, p, 1);
        p += __shfl_xor_sync(0xffffffffu, p, 2);
        if (j == 0) s_vn[i] = sqrt_approx(p);
    }
    __syncthreads();

    // ---- phase 0b: vectorized idx gather/scatter ----
    if (s_is64) {
#pragma unroll 1
        for (int s = tid; s < S_; s += T_) {
            int base = ((b * S_ + s) * O_ + o) * H_;
            const int4* p = (const int4*)idx + (base >> 1);
            int4 a0 = p[0], a1 = p[1], a2 = p[2], a3 = p[3], a4 = p[4];
            atomicOr(&s_mask[a0.x], 1u << 0);
            atomicOr(&s_mask[a0.z], 1u << 1);
            atomicOr(&s_mask[a1.x], 1u << 2);
            atomicOr(&s_mask[a1.z], 1u << 3);
            atomicOr(&s_mask[a2.x], 1u << 4);
            atomicOr(&s_mask[a2.z], 1u << 5);
            atomicOr(&s_mask[a3.x], 1u << 6);
            atomicOr(&s_mask[a3.z], 1u << 7);
            atomicOr(&s_mask[a4.x], 1u << 8);
            atomicOr(&s_mask[a4.z], 1u << 9);
        }
    } else {
#pragma unroll 1
        for (int s = tid; s < S_; s += T_) {
            int base = ((b * S_ + s) * O_ + o) * H_;
            const int2* p = (const int2*)idx + (base >> 1);
            int2 a0 = p[0], a1 = p[1], a2 = p[2], a3 = p[3], a4 = p[4];
            atomicOr(&s_mask[a0.x], 1u << 0);
            atomicOr(&s_mask[a0.y], 1u << 1);
            atomicOr(&s_mask[a1.x], 1u << 2);
            atomicOr(&s_mask[a1.y], 1u << 3);
            atomicOr(&s_mask[a2.x], 1u << 4);
            atomicOr(&s_mask[a2.y], 1u << 5);
            atomicOr(&s_mask[a3.x], 1u << 6);
            atomicOr(&s_mask[a3.y], 1u << 7);
            atomicOr(&s_mask[a4.x], 1u << 8);
            atomicOr(&s_mask[a4.y], 1u << 9);
        }
    }
    __syncthreads();

    // ---- phase 1: masked accumulation (warp = i-stripe; lane halves = h-halves) ----
    {
        const int d  = lane & 15;
        const int hb = (lane >> 4) * 5;       // 0 or 5
        float a0 = 0.f, a1 = 0.f, a2 = 0.f, a3 = 0.f, a4 = 0.f;
#pragma unroll 4
        for (int i = w; i < I_; i += 16) {    // 72 iterations
            unsigned m  = s_mask[i] >> hb;
            float    ud = __half2float(s_u16[i * D_ + d]);
            float    t0 = s_vn[i] * ud;
            if (m & 1u)  a0 += t0;
            if (m & 2u)  a1 += t0;
            if (m & 4u)  a2 += t0;
            if (m & 8u)  a3 += t0;
            if (m & 16u) a4 += t0;
        }
        atomicAdd(&s_MuNum[(hb + 0) * D_ + d], a0);
        atomicAdd(&s_MuNum[(hb + 1) * D_ + d], a1);
        atomicAdd(&s_MuNum[(hb + 2) * D_ + d], a2);
        atomicAdd(&s_MuNum[(hb + 3) * D_ + d], a3);
        atomicAdd(&s_MuNum[(hb + 4) * D_ + d], a4);
    }

    // ---- phase 1b: den pass (10 warps, one h each) ----
    if (w < H_) {
        unsigned bit = 1u << w;
        float dn = 0.f;
#pragma unroll 4
        for (int i = lane; i < I_; i += 32)
            if (s_mask[i] & bit) dn += s_vn[i];
#pragma unroll
        for (int off = 16; off > 0; off >>= 1)
            dn += __shfl_down_sync(0xffffffffu, dn, off);
        if (lane == 0) s_den[w] = dn;
    }
    __syncthreads();

    if (tid < H_ * D_) {
        int h = tid >> 4;
        s_Mu[h][tid & 15] = s_MuNum[tid] / s_den[h];
    }
    __syncthreads();
    if (tid < H_) {
        float m2 = 0.f;
#pragma unroll
        for (int dd = 0; dd < D_; dd++) { float x = s_Mu[tid][dd]; m2 += x * x; }
        s_mu2[tid] = m2;
    }
    __syncthreads();

    // ---- phase 2: butterfly losses (u16 -> fp32 in loop) ----
    {
        const int dq   = tid & 3;             // d-quarter owned
        const int g    = tid >> 2;            // 0..127 (i owner)
        const int sel  = lane & 1;
        const int bit1 = (lane >> 1) & 1;

#pragma unroll 1
        for (int grp = 0; grp < 2; grp++) {
            const int hb = grp * 4;
            float4 mq0 = *(const float4*)(&s_Mu[hb + 0][dq * 4]);
            float4 mq1 = *(const float4*)(&s_Mu[hb + 1][dq * 4]);
            float4 mq2 = *(const float4*)(&s_Mu[hb + 2][dq * 4]);
            float4 mq3 = *(const float4*)(&s_Mu[hb + 3][dq * 4]);
            const float u2 = s_mu2[hb + 2 * bit1 + sel];
            float lacc = 0.f;
#pragma unroll 1
            for (int k = 0; k < I_ / 128; k++) {      // 9 iterations
                int i = g + k * 128;
                const __half2* hp = (const __half2*)(s_u16 + i * D_ + dq * 4);
                float2 f0 = __half22float2(hp[0]);
                float2 f1 = __half22float2(hp[1]);
                float  v = s_vn[i];
                float sq = v * v;
                float p0 = f0.x*mq0.x + f0.y*mq0.y + f1.x*mq0.z + f1.y*mq0.w;
                float p1 = f0.x*mq1.x + f0.y*mq1.y + f1.x*mq1.z + f1.y*mq1.w;
                float p2 = f0.x*mq2.x + f0.y*mq2.y + f1.x*mq2.z + f1.y*mq2.w;
                float p3 = f0.x*mq3.x + f0.y*mq3.y + f1.x*mq3.z + f1.y*mq3.w;
                float keep_lo = sel ? p1 : p0;
                float send_lo = sel ? p0 : p1;
                float C_lo = keep_lo + __shfl_xor_sync(0xffffffffu, send_lo, 1);
                float keep_hi = sel ? p3 : p2;
                float send_hi = sel ? p2 : p3;
                float C_hi = keep_hi + __shfl_xor_sync(0xffffffffu, send_hi, 1);
                float keep2 = bit1 ? C_hi : C_lo;
                float send2 = bit1 ? C_lo : C_hi;
                float dot = keep2 + __shfl_xor_sync(0xffffffffu, send2, 2);
                lacc += sqrt_approx(fmaxf(sq + fmaf(-2.f, dot, u2), 0.f));
            }
            lacc += __shfl_down_sync(0xffffffffu, lacc, 16);
            lacc += __shfl_down_sync(0xffffffffu, lacc, 8);
            lacc += __shfl_down_sync(0xffffffffu, lacc, 4);
            if (lane < 4) s_loss[w][hb + lane] = lacc;
        }
        {
            float4 m8 = *(const float4*)(&s_Mu[8][dq * 4]);
            float4 m9 = *(const float4*)(&s_Mu[9][dq * 4]);
            const float u2 = s_mu2[8 + sel];
            float lacc = 0.f;
#pragma unroll 1
            for (int k = 0; k < I_ / 128; k++) {
                int i = g + k * 128;
                const __half2* hp = (const __half2*)(s_u16 + i * D_ + dq * 4);
                float2 f0 = __half22float2(hp[0]);
                float2 f1 = __half22float2(hp[1]);
                float  v = s_vn[i];
                float sq = v * v;
                float p8 = f0.x*m8.x + f0.y*m8.y + f1.x*m8.z + f1.y*m8.w;
                float p9 = f0.x*m9.x + f0.y*m9.y + f1.x*m9.z + f1.y*m9.w;
                float keep = sel ? p9 : p8;
                float send = sel ? p8 : p9;
                float C = keep + __shfl_xor_sync(0xffffffffu, send, 1);
                float dot = C + __shfl_xor_sync(0xffffffffu, C, 2);
                lacc += sqrt_approx(fmaxf(sq + fmaf(-2.f, dot, u2), 0.f));
            }
            lacc += __shfl_down_sync(0xffffffffu, lacc, 16);
            lacc += __shfl_down_sync(0xffffffffu, lacc, 8);
            lacc += __shfl_down_sync(0xffffffffu, lacc, 4);
            if (lane < 2) s_loss[w][8 + lane] = lacc;
        }
    }
    __syncthreads();

    // ---- argmin + output: warp 0 only (shfl min-reduce) ----
    if (w == 0) {
        float myv = 3.4e38f;
        int   myh = 0;
        if (lane < H_) {
            float l = 0.f;
#pragma unroll
            for (int ww = 0; ww < 16; ww++) l += s_loss[ww][lane];
            myv = l; myh = lane;
        }
#pragma unroll
        for (int off = 16; off > 0; off >>= 1) {
            float ov = __shfl_xor_sync(0xffffffffu, myv, off);
            int   oh = __shfl_xor_sync(0xffffffffu, myh, off);
            if (ov < myv || (ov == myv && oh < myh)) { myv = ov; myh = oh; }
        }
        if (lane < D_) out[(size_t)bo * D_ + lane] = s_Mu[myh][lane];
    }
}

// ---------------------------------------------------------------------------
extern "C" void kernel_launch(void* const* d_in, const int* in_sizes, int n_in,
                              void* d_out, int out_size) {
    const float* u   = (const float*)d_in[0];
    const int*   idx = (const int*)d_in[1];
    float*       out = (float*)d_out;
    (void)in_sizes; (void)n_in; (void)out_size;

    static int attr_set = 0;
    if (!attr_set) {
        cudaFuncSetAttribute(fused_kernel,
                             cudaFuncAttributeMaxDynamicSharedMemorySize, SMEM_BYTES);
        attr_set = 1;
    }
    fused_kernel<<<B_ * O_, T_, SMEM_BYTES>>>(u, idx, out);
}

// round 17
// speedup vs baseline: 1.9856x; 1.0092x over previous
#include <cuda_runtime.h>
#include <cuda_fp16.h>
#include <cstdint>

#define B_ 32
#define I_ 1152
#define IH 576          // i-half per CTA
#define O_ 10
#define D_ 16
#define H_ 10
#define S_ 922
#define SH 461          // samples per CTA
#define T_ 256
#define RS (O_ * D_)    // 160

// dynamic smem layout (bytes)
//   u16   [576][16] half = 18432
//   maskF [1152] u32     =  4608   (full range, local scatter + DSMEM merge)
//   vn    [576]  f32     =  2304
//   num   [H*D]  f32     =   640
//   den   [16]   f32     =    64
//   lossH [16]   f32     =    64
#define OFFB_U16   0
#define OFFB_MASKF 18432
#define OFFB_VN    23040
#define OFFB_NUM   25344
#define OFFB_DEN   25984
#define OFFB_LOSS  26048
#define SMEM_BYTES 26112

__device__ __forceinline__ float sqrt_approx(float x) {
    float y;
    asm("sqrt.approx.f32 %0, %1;" : "=f"(y) : "f"(x));
    return y;
}
__device__ __forceinline__ uint32_t mapa_peer(uint32_t addr, uint32_t rank) {
    uint32_t r;
    asm("mapa.shared::cluster.u32 %0, %1, %2;" : "=r"(r) : "r"(addr), "r"(rank));
    return r;
}
__device__ __forceinline__ float ld_cluster_f32(uint32_t addr) {
    float v;
    asm volatile("ld.shared::cluster.f32 %0, [%1];" : "=f"(v) : "r"(addr));
    return v;
}
__device__ __forceinline__ unsigned ld_cluster_u32(uint32_t addr) {
    unsigned v;
    asm volatile("ld.shared::cluster.u32 %0, [%1];" : "=r"(v) : "r"(addr));
    return v;
}
#define CLUSTER_SYNC() do { \
    asm volatile("barrier.cluster.arrive.aligned;" ::: "memory"); \
    asm volatile("barrier.cluster.wait.aligned;"   ::: "memory"); \
} while (0)

// ---------------------------------------------------------------------------
// Cluster of 2 CTAs per (b,o); each owns an i-half as an fp16 tile (~26KB)
// -> 5 CTAs/SM capacity -> all 640 CTAs in ONE wave, max 2.5 units/SM.
//  0:  probe; zero full mask; load u half (fp32 LDG) -> vn fp32 + u16 smem
//  0b: scatter own SAMPLE-half locally (2 iters); bulk DSMEM mask merge
//  1:  masked accumulation over own i-half -> partial num/den
//  Mu: DSMEM exchange num/den -> full Mu both CTAs; mu2
//  2:  butterfly losses (grp4,grp4,grp2) over own half
//  rank0: argmin with peer loss, output
// ---------------------------------------------------------------------------
__global__ void __cluster_dims__(2, 1, 1) __launch_bounds__(T_, 5)
fused_kernel(const float* __restrict__ u, const int* __restrict__ idx,
             float* __restrict__ out) {
    extern __shared__ char smraw[];
    __half*   s_u16   = (__half*)(smraw + OFFB_U16);       // [576][16]
    unsigned* s_maskF = (unsigned*)(smraw + OFFB_MASKF);   // [1152]
    float*    s_vn    = (float*)(smraw + OFFB_VN);         // [576]
    float*    s_num   = (float*)(smraw + OFFB_NUM);        // [H][D]
    float*    s_den   = (float*)(smraw + OFFB_DEN);        // [H]
    float*    s_lossH = (float*)(smraw + OFFB_LOSS);       // [H]

    __shared__ __align__(16) float s_Mu[H_][D_];
    __shared__ float s_mu2[H_];
    __shared__ float s_loss[8][H_];
    __shared__ int   s_is64;

    uint32_t rank;
    asm("mov.u32 %0, %%cluster_ctarank;" : "=r"(rank));
    const int bo   = blockIdx.x >> 1;
    const int b    = bo / O_;
    const int o    = bo % O_;
    const int i0   = (int)rank * IH;
    const int tid  = threadIdx.x;
    const int lane = tid & 31;
    const int w    = tid >> 5;      // 8 warps

    const float* ub = u + ((size_t)b * I_ * O_ + o) * D_;

    // ---- phase 0: dtype probe + zero full mask + load u half -> vn + u16 ----
    if (w == 0) {
        unsigned v = ((const unsigned*)idx)[2 * lane + 1]
                   | ((const unsigned*)idx)[2 * (lane + 32) + 1];
        unsigned r = __reduce_or_sync(0xffffffffu, v);
        if (lane == 0) s_is64 = (r == 0u) ? 1 : 0;
    }
    for (int j = tid; j < I_; j += T_) s_maskF[j] = 0u;
    if (tid < H_ * D_) s_num[tid] = 0.f;

#pragma unroll 1
    for (int e = tid; e < IH * 4; e += T_) {        // 9 exact iterations
        int row = e >> 2, j = e & 3;
        float4 q = *(const float4*)(ub + (size_t)(i0 + row) * RS + j * 4);
        __half2* hp = (__half2*)(s_u16 + row * D_ + j * 4);
        hp[0] = __floats2half2_rn(q.x, q.y);
        hp[1] = __floats2half2_rn(q.z, q.w);
        float p = q.x * q.x + q.y * q.y + q.z * q.z + q.w * q.w;
        p += __shfl_xor_sync(0xffffffffu, p, 1);
        p += __shfl_xor_sync(0xffffffffu, p, 2);
        if (j == 0) s_vn[row] = sqrt_approx(p);
    }
    __syncthreads();

    // ---- phase 0b: scatter own sample-half, LOCAL + unfiltered ----
    if (s_is64) {
#pragma unroll 1
        for (int s = (int)rank * SH + tid; s < (int)rank * SH + SH; s += T_) {
            int base = ((b * S_ + s) * O_ + o) * H_;
            const int4* p = (const int4*)idx + (base >> 1);
            int4 a0 = p[0], a1 = p[1], a2 = p[2], a3 = p[3], a4 = p[4];
            atomicOr(&s_maskF[a0.x], 1u << 0);
            atomicOr(&s_maskF[a0.z], 1u << 1);
            atomicOr(&s_maskF[a1.x], 1u << 2);
            atomicOr(&s_maskF[a1.z], 1u << 3);
            atomicOr(&s_maskF[a2.x], 1u << 4);
            atomicOr(&s_maskF[a2.z], 1u << 5);
            atomicOr(&s_maskF[a3.x], 1u << 6);
            atomicOr(&s_maskF[a3.z], 1u << 7);
            atomicOr(&s_maskF[a4.x], 1u << 8);
            atomicOr(&s_maskF[a4.z], 1u << 9);
        }
    } else {
#pragma unroll 1
        for (int s = (int)rank * SH + tid; s < (int)rank * SH + SH; s += T_) {
            int base = ((b * S_ + s) * O_ + o) * H_;
            const int2* p = (const int2*)idx + (base >> 1);
            int2 a0 = p[0], a1 = p[1], a2 = p[2], a3 = p[3], a4 = p[4];
            atomicOr(&s_maskF[a0.x], 1u << 0);
            atomicOr(&s_maskF[a0.y], 1u << 1);
            atomicOr(&s_maskF[a1.x], 1u << 2);
            atomicOr(&s_maskF[a1.y], 1u << 3);
            atomicOr(&s_maskF[a2.x], 1u << 4);
            atomicOr(&s_maskF[a2.y], 1u << 5);
            atomicOr(&s_maskF[a3.x], 1u << 6);
            atomicOr(&s_maskF[a3.y], 1u << 7);
            atomicOr(&s_maskF[a4.x], 1u << 8);
            atomicOr(&s_maskF[a4.y], 1u << 9);
        }
    }
    __syncthreads();
    CLUSTER_SYNC();     // peer's local scatter visible

    // ---- bulk merge: my-half mask |= peer's bits for my i-range ----
    {
        uint32_t myBase   = (uint32_t)__cvta_generic_to_shared(s_maskF);
        uint32_t peerBase = mapa_peer(myBase, rank ^ 1u);
#pragma unroll 1
        for (int i = tid; i < IH; i += T_) {        // 2.25 iters
            unsigned pm = ld_cluster_u32(peerBase + 4u * (i0 + i));
            s_maskF[i0 + i] |= pm;
        }
    }
    __syncthreads();

    // ---- phase 1: masked accumulation over own i-half ----
    {
        const int d  = lane & 15;
        const int hb = (lane >> 4) * 5;
        float a0 = 0.f, a1 = 0.f, a2 = 0.f, a3 = 0.f, a4 = 0.f;
#pragma unroll 4
        for (int ii = w; ii < IH; ii += 8) {        // 72 iterations
            unsigned m  = s_maskF[i0 + ii] >> hb;
            float    ud = __half2float(s_u16[ii * D_ + d]);
            float    t0 = s_vn[ii] * ud;
            if (m & 1u)  a0 += t0;
            if (m & 2u)  a1 += t0;
            if (m & 4u)  a2 += t0;
            if (m & 8u)  a3 += t0;
            if (m & 16u) a4 += t0;
        }
        atomicAdd(&s_num[(hb + 0) * D_ + d], a0);
        atomicAdd(&s_num[(hb + 1) * D_ + d], a1);
        atomicAdd(&s_num[(hb + 2) * D_ + d], a2);
        atomicAdd(&s_num[(hb + 3) * D_ + d], a3);
        atomicAdd(&s_num[(hb + 4) * D_ + d], a4);
    }
    // den: warps 0..7 -> h=w; warps 0,1 also h=8,9
    {
#pragma unroll 1
        for (int rep = 0; rep < 2; rep++) {
            if (rep == 1 && w >= 2) break;
            int h = (rep == 0) ? w : 8 + w;
            unsigned bit = 1u << h;
            float dn = 0.f;
#pragma unroll 4
            for (int ii = lane; ii < IH; ii += 32)
                if (s_maskF[i0 + ii] & bit) dn += s_vn[ii];
#pragma unroll
            for (int off = 16; off > 0; off >>= 1)
                dn += __shfl_down_sync(0xffffffffu, dn, off);
            if (lane == 0) s_den[h] = dn;
        }
    }
    __syncthreads();
    CLUSTER_SYNC();     // partial num/den visible cluster-wide

    // ---- exchange num/den; full Mu in both CTAs ----
    if (tid < H_ * D_) {
        int h = tid >> 4;
        uint32_t pn = mapa_peer((uint32_t)__cvta_generic_to_shared(&s_num[tid]),
                                rank ^ 1u);
        uint32_t pd = mapa_peer((uint32_t)__cvta_generic_to_shared(&s_den[h]),
                                rank ^ 1u);
        float num = s_num[tid] + ld_cluster_f32(pn);
        float den = s_den[h]   + ld_cluster_f32(pd);
        s_Mu[h][tid & 15] = num / den;
    }
    __syncthreads();
    if (tid < H_) {
        float m2 = 0.f;
#pragma unroll
        for (int dd = 0; dd < D_; dd++) { float x = s_Mu[tid][dd]; m2 += x * x; }
        s_mu2[tid] = m2;
    }
    __syncthreads();

    // ---- phase 2: butterfly losses over own half (u16 -> fp32) ----
    {
        const int dq   = tid & 3;
        const int g    = tid >> 2;            // 0..63
        const int sel  = lane & 1;
        const int bit1 = (lane >> 1) & 1;

#pragma unroll 1
        for (int grp = 0; grp < 2; grp++) {
            const int hb = grp * 4;
            float4 mq0 = *(const float4*)(&s_Mu[hb + 0][dq * 4]);
            float4 mq1 = *(const float4*)(&s_Mu[hb + 1][dq * 4]);
            float4 mq2 = *(const float4*)(&s_Mu[hb + 2][dq * 4]);
            float4 mq3 = *(const float4*)(&s_Mu[hb + 3][dq * 4]);
            const float u2 = s_mu2[hb + 2 * bit1 + sel];
            float lacc = 0.f;
#pragma unroll 1
            for (int k = 0; k < IH / 64; k++) {   // 9 iterations
                int i = g + k * 64;
                const __half2* hp = (const __half2*)(s_u16 + i * D_ + dq * 4);
                float2 f0 = __half22float2(hp[0]);
                float2 f1 = __half22float2(hp[1]);
                float  v = s_vn[i];
                float sq = v * v;
                float p0 = f0.x*mq0.x + f0.y*mq0.y + f1.x*mq0.z + f1.y*mq0.w;
                float p1 = f0.x*mq1.x + f0.y*mq1.y + f1.x*mq1.z + f1.y*mq1.w;
                float p2 = f0.x*mq2.x + f0.y*mq2.y + f1.x*mq2.z + f1.y*mq2.w;
                float p3 = f0.x*mq3.x + f0.y*mq3.y + f1.x*mq3.z + f1.y*mq3.w;
                float keep_lo = sel ? p1 : p0;
                float send_lo = sel ? p0 : p1;
                float C_lo = keep_lo + __shfl_xor_sync(0xffffffffu, send_lo, 1);
                float keep_hi = sel ? p3 : p2;
                float send_hi = sel ? p2 : p3;
                float C_hi = keep_hi + __shfl_xor_sync(0xffffffffu, send_hi, 1);
                float keep2 = bit1 ? C_hi : C_lo;
                float send2 = bit1 ? C_lo : C_hi;
                float dot = keep2 + __shfl_xor_sync(0xffffffffu, send2, 2);
                lacc += sqrt_approx(fmaxf(sq + fmaf(-2.f, dot, u2), 0.f));
            }
            lacc += __shfl_down_sync(0xffffffffu, lacc, 16);
            lacc += __shfl_down_sync(0xffffffffu, lacc, 8);
            lacc += __shfl_down_sync(0xffffffffu, lacc, 4);
            if (lane < 4) s_loss[w][hb + lane] = lacc;
        }
        {
            float4 m8 = *(const float4*)(&s_Mu[8][dq * 4]);
            float4 m9 = *(const float4*)(&s_Mu[9][dq * 4]);
            const float u2 = s_mu2[8 + sel];
            float lacc = 0.f;
#pragma unroll 1
            for (int k = 0; k < IH / 64; k++) {
                int i = g + k * 64;
                const __half2* hp = (const __half2*)(s_u16 + i * D_ + dq * 4);
                float2 f0 = __half22float2(hp[0]);
                float2 f1 = __half22float2(hp[1]);
                float  v = s_vn[i];
                float sq = v * v;
                float p8 = f0.x*m8.x + f0.y*m8.y + f1.x*m8.z + f1.y*m8.w;
                float p9 = f0.x*m9.x + f0.y*m9.y + f1.x*m9.z + f1.y*m9.w;
                float keep = sel ? p9 : p8;
                float send = sel ? p8 : p9;
                float C = keep + __shfl_xor_sync(0xffffffffu, send, 1);
                float dot = C + __shfl_xor_sync(0xffffffffu, C, 2);
                lacc += sqrt_approx(fmaxf(sq + fmaf(-2.f, dot, u2), 0.f));
            }
            lacc += __shfl_down_sync(0xffffffffu, lacc, 16);
            lacc += __shfl_down_sync(0xffffffffu, lacc, 8);
            lacc += __shfl_down_sync(0xffffffffu, lacc, 4);
            if (lane < 2) s_loss[w][8 + lane] = lacc;
        }
    }
    __syncthreads();
    if (tid < H_) {
        float l = 0.f;
#pragma unroll
        for (int ww = 0; ww < 8; ww++) l += s_loss[ww][tid];
        s_lossH[tid] = l;
    }
    __syncthreads();
    CLUSTER_SYNC();     // loss halves visible

    // ---- rank 0: argmin with peer loss + output ----
    if (rank == 0 && w == 0) {
        float myv = 3.4e38f;
        int   myh = 0;
        if (lane < H_) {
            uint32_t pl = mapa_peer(
                (uint32_t)__cvta_generic_to_shared(&s_lossH[lane]), 1u);
            myv = s_lossH[lane] + ld_cluster_f32(pl);
            myh = lane;
        }
#pragma unroll
        for (int off = 16; off > 0; off >>= 1) {
            float ov = __shfl_xor_sync(0xffffffffu, myv, off);
            int   oh = __shfl_xor_sync(0xffffffffu, myh, off);
            if (ov < myv || (ov == myv && oh < myh)) { myv = ov; myh = oh; }
        }
        if (lane < D_) out[(size_t)bo * D_ + lane] = s_Mu[myh][lane];
    }
    CLUSTER_SYNC();     // peer smem must outlive rank0's reads
}

// ---------------------------------------------------------------------------
extern "C" void kernel_launch(void* const* d_in, const int* in_sizes, int n_in,
                              void* d_out, int out_size) {
    const float* u   = (const float*)d_in[0];
    const int*   idx = (const int*)d_in[1];
    float*       out = (float*)d_out;
    (void)in_sizes; (void)n_in; (void)out_size;

    static int attr_set = 0;
    if (!attr_set) {
        cudaFuncSetAttribute(fused_kernel,
                             cudaFuncAttributeMaxDynamicSharedMemorySize, SMEM_BYTES);
        attr_set = 1;
    }
    fused_kernel<<<2 * B_ * O_, T_, SMEM_BYTES>>>(u, idx, out);
}